// round 12
// baseline (speedup 1.0000x reference)
#include <cuda_runtime.h>
#include <cuda_bf16.h>
#include <cstdint>

#define N_NODES 100000
#define N_EDGES 800000
#define K_DIM   128

typedef unsigned long long u64;

// -------- scratch (device globals; no allocation allowed) --------
__device__ __align__(16) float g_dinv [N_NODES];
__device__ __align__(16) float g_t    [N_NODES * 128];
__device__ __align__(16) float g_h1   [N_NODES * 128];
__device__ __align__(16) float g_h2   [N_NODES * 128];
__device__ __align__(16) int   g_src  [N_EDGES];
__device__ __align__(16) int   g_dst  [N_EDGES];
__device__ __align__(16) int   g_csr  [N_EDGES];
__device__ __align__(16) int   g_cnt  [N_NODES];
__device__ __align__(16) int   g_start[N_NODES];
__device__ __align__(16) int   g_cur  [N_NODES];
__device__ int g_total;

__device__ __forceinline__ uint32_t smem_u32(const void* p) {
    uint32_t a;
    asm("{ .reg .u64 t; cvta.to.shared.u64 t, %1; cvt.u32.u64 %0, t; }" : "=r"(a) : "l"(p));
    return a;
}

#define LDMX4(r0, r1, r2, r3, addr) \
    asm volatile("ldmatrix.sync.aligned.m8n8.x4.shared.b16 {%0,%1,%2,%3}, [%4];" \
                 : "=r"(r0), "=r"(r1), "=r"(r2), "=r"(r3) : "r"(addr))

#define MMA16816(d, a, b0, b1) \
    asm volatile("mma.sync.aligned.m16n8k16.row.col.f32.bf16.bf16.f32 " \
                 "{%0,%1,%2,%3}, {%4,%5,%6,%7}, {%8,%9}, {%0,%1,%2,%3};" \
                 : "+f"((d)[0]), "+f"((d)[1]), "+f"((d)[2]), "+f"((d)[3]) \
                 : "r"((a)[0]), "r"((a)[1]), "r"((a)[2]), "r"((a)[3]), \
                   "r"(b0), "r"(b1))

__device__ __forceinline__ void split_bf16(float v, unsigned short& hi, unsigned short& lo) {
    __nv_bfloat16 h = __float2bfloat16_rn(v);
    hi = __bfloat16_as_ushort(h);
    lo = __bfloat16_as_ushort(__float2bfloat16_rn(v - __bfloat162float(h)));
}

// ================= preprocessing =================
__global__ void zero_kernel(int* __restrict__ cnt, int* __restrict__ total) {
    int i = blockIdx.x * blockDim.x + threadIdx.x;
    if (i < N_NODES) cnt[i] = 0;
    if (i == 0) *total = 0;
}

// dtype detect inlined: if buffer is int64, high words of first 64 values are 0.
__global__ void convert_hist_kernel(const int* __restrict__ ei32,
                                    int* __restrict__ src, int* __restrict__ dst,
                                    int* __restrict__ cnt) {
    int lane = threadIdx.x & 31;
    int hi = ei32[2 * lane + 1] | ei32[2 * (lane + 32) + 1];
    bool is64 = !__any_sync(0xffffffffu, hi != 0);

    int e = blockIdx.x * blockDim.x + threadIdx.x;
    if (e >= N_EDGES) return;
    int s, d;
    if (is64) { s = ei32[2 * e]; d = ei32[2 * (N_EDGES + e)]; }
    else      { s = ei32[e];     d = ei32[N_EDGES + e]; }
    src[e] = s;
    dst[e] = d;
    atomicAdd(&cnt[d], 1);
}

__global__ void dinv_seg_kernel(const int* __restrict__ cnt, float* __restrict__ dinv,
                                int* __restrict__ start, int* __restrict__ cur,
                                int* __restrict__ total) {
    int i = blockIdx.x * blockDim.x + threadIdx.x;
    if (i < N_NODES) {
        int c = cnt[i];
        dinv[i] = rsqrtf((float)c + 1.0f);
        int s = atomicAdd(total, c);
        start[i] = s;
        cur[i]   = s;
    }
}

__global__ void scatter_kernel(const int* __restrict__ src, const int* __restrict__ dst,
                               int* __restrict__ cur, int* __restrict__ csr) {
    int e = blockIdx.x * blockDim.x + threadIdx.x;
    if (e < N_EDGES) {
        int pos = atomicAdd(&cur[dst[e]], 1);
        csr[pos] = src[e];
    }
}

// ================= tensor-core GEMM (HMMA): T = relu?(A) @ W ========
template <int BN, bool RELU>
__global__ __launch_bounds__(256)
void gemm_mma_kernel(const float* __restrict__ A, const float* __restrict__ W,
                     float* __restrict__ T)
{
    constexpr int LDA     = 136;
    constexpr int A_BYTES = 128 * LDA * 2;
    constexpr int B_BYTES = BN  * LDA * 2;
    constexpr int NCH     = BN / 8;

    extern __shared__ __align__(16) char smem[];
    __nv_bfloat16* Ahi = reinterpret_cast<__nv_bfloat16*>(smem);
    __nv_bfloat16* Alo = reinterpret_cast<__nv_bfloat16*>(smem + A_BYTES);
    __nv_bfloat16* Bhi = reinterpret_cast<__nv_bfloat16*>(smem + 2 * A_BYTES);
    __nv_bfloat16* Blo = reinterpret_cast<__nv_bfloat16*>(smem + 2 * A_BYTES + B_BYTES);

    const int tid   = threadIdx.x;
    const int wid   = tid >> 5;
    const int lane  = tid & 31;
    const int tile0 = blockIdx.x * 128;

    #pragma unroll
    for (int it = 0; it < 16; it++) {
        int f  = it * 256 + tid;
        int r  = f >> 5;
        int c  = (f & 31) * 4;
        int gr = tile0 + r;
        if (gr >= N_NODES) gr = N_NODES - 1;
        float4 v = *reinterpret_cast<const float4*>(A + (size_t)gr * K_DIM + c);
        if (RELU) {
            v.x = fmaxf(v.x, 0.f); v.y = fmaxf(v.y, 0.f);
            v.z = fmaxf(v.z, 0.f); v.w = fmaxf(v.w, 0.f);
        }
        unsigned short h0, h1, h2, h3, l0, l1, l2, l3;
        split_bf16(v.x, h0, l0); split_bf16(v.y, h1, l1);
        split_bf16(v.z, h2, l2); split_bf16(v.w, h3, l3);
        u64 hp = (u64)h0 | ((u64)h1 << 16) | ((u64)h2 << 32) | ((u64)h3 << 48);
        u64 lp = (u64)l0 | ((u64)l1 << 16) | ((u64)l2 << 32) | ((u64)l3 << 48);
        *reinterpret_cast<u64*>(&Ahi[r * LDA + c]) = hp;
        *reinterpret_cast<u64*>(&Alo[r * LDA + c]) = lp;
    }

    #pragma unroll
    for (int it = 0; it < BN / 8; it++) {
        int f  = it * 256 + tid;
        int k  = f / (BN / 4);
        int n0 = (f % (BN / 4)) * 4;
        float4 v = *reinterpret_cast<const float4*>(W + (size_t)k * BN + n0);
        float vv[4] = {v.x, v.y, v.z, v.w};
        #pragma unroll
        for (int j = 0; j < 4; j++) {
            unsigned short h, l;
            split_bf16(vv[j], h, l);
            Bhi[(n0 + j) * LDA + k] = __ushort_as_bfloat16(h);
            Blo[(n0 + j) * LDA + k] = __ushort_as_bfloat16(l);
        }
    }
    __syncthreads();

    const uint32_t a_off = (uint32_t)((wid * 16 + (lane & 15)) * LDA + (lane >> 4) * 8) * 2;
    const uint32_t ahi_base = smem_u32(Ahi) + a_off;
    const uint32_t alo_base = smem_u32(Alo) + a_off;
    const uint32_t b_off = (uint32_t)(((lane & 7) + (lane >> 4) * 8) * LDA + ((lane >> 3) & 1) * 8) * 2;
    const uint32_t bhi_base = smem_u32(Bhi) + b_off;
    const uint32_t blo_base = smem_u32(Blo) + b_off;

    float acc[NCH][4];
    #pragma unroll
    for (int i = 0; i < NCH; i++)
        #pragma unroll
        for (int j = 0; j < 4; j++) acc[i][j] = 0.f;

    #pragma unroll
    for (int ks = 0; ks < 8; ks++) {
        const uint32_t kb = ks * 32;
        uint32_t ah[4], al[4];
        LDMX4(ah[0], ah[1], ah[2], ah[3], ahi_base + kb);
        LDMX4(al[0], al[1], al[2], al[3], alo_base + kb);
        #pragma unroll
        for (int nb = 0; nb < BN / 16; nb++) {
            const uint32_t nbo = (uint32_t)(nb * 16 * LDA) * 2 + kb;
            uint32_t bh[4], bl[4];
            LDMX4(bh[0], bh[1], bh[2], bh[3], bhi_base + nbo);
            LDMX4(bl[0], bl[1], bl[2], bl[3], blo_base + nbo);
            MMA16816(acc[2 * nb],     ah, bh[0], bh[1]);
            MMA16816(acc[2 * nb + 1], ah, bh[2], bh[3]);
            MMA16816(acc[2 * nb],     ah, bl[0], bl[1]);
            MMA16816(acc[2 * nb + 1], ah, bl[2], bl[3]);
            MMA16816(acc[2 * nb],     al, bh[0], bh[1]);
            MMA16816(acc[2 * nb + 1], al, bh[2], bh[3]);
        }
    }

    const int g = lane >> 2, t = lane & 3;
    const int rowA = tile0 + wid * 16 + g;
    const int rowB = rowA + 8;
    #pragma unroll
    for (int nc = 0; nc < NCH; nc++) {
        int col = nc * 8 + 2 * t;
        if (rowA < N_NODES)
            *reinterpret_cast<float2*>(T + (size_t)rowA * BN + col) =
                make_float2(acc[nc][0], acc[nc][1]);
        if (rowB < N_NODES)
            *reinterpret_cast<float2*>(T + (size_t)rowB * BN + col) =
                make_float2(acc[nc][2], acc[nc][3]);
    }
}

// ================= gather aggregation (unroll 8, hoisted index loads) =======
template <int F>
__global__ __launch_bounds__(256)
void agg_kernel(const int* __restrict__ start, const int* __restrict__ cnt,
                const int* __restrict__ csr, const float* __restrict__ dinv,
                const float* __restrict__ T, const float* __restrict__ bias,
                float* __restrict__ OUT)
{
    constexpr int LPN = F / 4;
    int gid  = blockIdx.x * blockDim.x + threadIdx.x;
    int node = gid / LPN;
    int lane = gid % LPN;
    if (node >= N_NODES) return;

    const int s = start[node];
    const int c = cnt[node];
    const int off = lane * 4;

    float4 acc = make_float4(0.f, 0.f, 0.f, 0.f);
    int j = 0;
    for (; j + 8 <= c; j += 8) {
        int sid[8];
        #pragma unroll
        for (int u = 0; u < 8; u++) sid[u] = csr[s + j + u];
        float w[8];
        #pragma unroll
        for (int u = 0; u < 8; u++) w[u] = dinv[sid[u]];
        float4 v[8];
        #pragma unroll
        for (int u = 0; u < 8; u++)
            v[u] = *reinterpret_cast<const float4*>(T + (size_t)sid[u] * F + off);
        #pragma unroll
        for (int u = 0; u < 8; u++) {
            acc.x = fmaf(v[u].x, w[u], acc.x); acc.y = fmaf(v[u].y, w[u], acc.y);
            acc.z = fmaf(v[u].z, w[u], acc.z); acc.w = fmaf(v[u].w, w[u], acc.w);
        }
    }
    for (; j + 2 <= c; j += 2) {
        int s0 = csr[s + j], s1 = csr[s + j + 1];
        float w0 = dinv[s0], w1 = dinv[s1];
        float4 v0 = *reinterpret_cast<const float4*>(T + (size_t)s0 * F + off);
        float4 v1 = *reinterpret_cast<const float4*>(T + (size_t)s1 * F + off);
        acc.x = fmaf(v0.x, w0, acc.x); acc.y = fmaf(v0.y, w0, acc.y);
        acc.z = fmaf(v0.z, w0, acc.z); acc.w = fmaf(v0.w, w0, acc.w);
        acc.x = fmaf(v1.x, w1, acc.x); acc.y = fmaf(v1.y, w1, acc.y);
        acc.z = fmaf(v1.z, w1, acc.z); acc.w = fmaf(v1.w, w1, acc.w);
    }
    if (j < c) {
        int s0 = csr[s + j];
        float w0 = dinv[s0];
        float4 v0 = *reinterpret_cast<const float4*>(T + (size_t)s0 * F + off);
        acc.x = fmaf(v0.x, w0, acc.x); acc.y = fmaf(v0.y, w0, acc.y);
        acc.z = fmaf(v0.z, w0, acc.z); acc.w = fmaf(v0.w, w0, acc.w);
    }

    float dv = dinv[node];
    float sn = dv * dv;
    float4 ts = *reinterpret_cast<const float4*>(T + (size_t)node * F + off);
    float4 bv = *reinterpret_cast<const float4*>(bias + off);
    float4 o;
    o.x = fmaf(acc.x, dv, fmaf(ts.x, sn, bv.x));
    o.y = fmaf(acc.y, dv, fmaf(ts.y, sn, bv.y));
    o.z = fmaf(acc.z, dv, fmaf(ts.z, sn, bv.z));
    o.w = fmaf(acc.w, dv, fmaf(ts.w, sn, bv.w));
    *reinterpret_cast<float4*>(OUT + (size_t)node * F + off) = o;
}

// ================= launch =================
extern "C" void kernel_launch(void* const* d_in, const int* in_sizes, int n_in,
                              void* d_out, int out_size)
{
    const float* x    = (const float*)d_in[0];
    const int*   ei32 = (const int*)d_in[1];
    const float* W1 = (const float*)d_in[2];
    const float* b1 = (const float*)d_in[3];
    const float* W2 = (const float*)d_in[4];
    const float* b2 = (const float*)d_in[5];
    const float* W3 = (const float*)d_in[6];
    const float* b3 = (const float*)d_in[7];
    float* out = (float*)d_out;

    float *dinv, *t, *h1, *h2;
    int *src, *dst, *csr, *cnt, *start, *cur, *total;
    cudaGetSymbolAddress((void**)&dinv,  g_dinv);
    cudaGetSymbolAddress((void**)&t,     g_t);
    cudaGetSymbolAddress((void**)&h1,    g_h1);
    cudaGetSymbolAddress((void**)&h2,    g_h2);
    cudaGetSymbolAddress((void**)&src,   g_src);
    cudaGetSymbolAddress((void**)&dst,   g_dst);
    cudaGetSymbolAddress((void**)&csr,   g_csr);
    cudaGetSymbolAddress((void**)&cnt,   g_cnt);
    cudaGetSymbolAddress((void**)&start, g_start);
    cudaGetSymbolAddress((void**)&cur,   g_cur);
    cudaGetSymbolAddress((void**)&total, g_total);

    const int TB = 256;
    const int NGRID = (N_NODES + TB - 1) / TB;
    const int EGRID = (N_EDGES + TB - 1) / TB;

    // launch order chosen so the 6th launch (ncu -s 5 -c 1) is agg1
    zero_kernel        <<<NGRID, TB>>>(cnt, total);                 // 1
    convert_hist_kernel<<<EGRID, TB>>>(ei32, src, dst, cnt);        // 2
    dinv_seg_kernel    <<<NGRID, TB>>>(cnt, dinv, start, cur, total); // 3
    scatter_kernel     <<<EGRID, TB>>>(src, dst, cur, csr);         // 4

    const int GTILES = (N_NODES + 127) / 128;
    const int SMEM128 = 4 * (128 * 136 * 2);
    const int SMEM64  = 2 * (128 * 136 * 2) + 2 * (64 * 136 * 2);
    static bool attr_done = false;
    if (!attr_done) {
        cudaFuncSetAttribute(gemm_mma_kernel<128, false>,
                             cudaFuncAttributeMaxDynamicSharedMemorySize, SMEM128);
        cudaFuncSetAttribute(gemm_mma_kernel<128, true>,
                             cudaFuncAttributeMaxDynamicSharedMemorySize, SMEM128);
        cudaFuncSetAttribute(gemm_mma_kernel<64, true>,
                             cudaFuncAttributeMaxDynamicSharedMemorySize, SMEM64);
        attr_done = true;
    }

    const int agrid128 = (N_NODES * 32 + TB - 1) / TB;
    const int agrid64  = (N_NODES * 16 + TB - 1) / TB;

    gemm_mma_kernel<128, false><<<GTILES, 256, SMEM128>>>(x, W1, t);   // 5
    agg_kernel<128><<<agrid128, TB>>>(start, cnt, csr, dinv, t, b1, h1); // 6 <- profiled
    gemm_mma_kernel<128, true><<<GTILES, 256, SMEM128>>>(h1, W2, t);
    agg_kernel<128><<<agrid128, TB>>>(start, cnt, csr, dinv, t, b2, h2);
    gemm_mma_kernel<64, true><<<GTILES, 256, SMEM64>>>(h2, W3, t);
    agg_kernel<64><<<agrid64, TB>>>(start, cnt, csr, dinv, t, b3, out);
}

// round 13
// speedup vs baseline: 1.3201x; 1.3201x over previous
#include <cuda_runtime.h>
#include <cuda_bf16.h>
#include <cstdint>

#define N_NODES 100000
#define N_EDGES 800000
#define K_DIM   128
#define LDA     136

typedef unsigned long long u64;

// -------- scratch (device globals; no allocation allowed) --------
__device__ __align__(16) float g_dinv [N_NODES];
__device__ __align__(16) float g_t    [N_NODES * 128];   // T' = (A@W)*dinv[row]
__device__ __align__(16) __nv_bfloat16 g_hhi[N_NODES * 128];
__device__ __align__(16) __nv_bfloat16 g_hlo[N_NODES * 128];
__device__ __align__(16) __nv_bfloat16 g_h2hi[N_NODES * 128];
__device__ __align__(16) __nv_bfloat16 g_h2lo[N_NODES * 128];
__device__ __align__(16) __nv_bfloat16 g_whi[3 * 128 * LDA];
__device__ __align__(16) __nv_bfloat16 g_wlo[3 * 128 * LDA];
__device__ __align__(16) int   g_src  [N_EDGES];
__device__ __align__(16) int   g_dst  [N_EDGES];
__device__ __align__(16) int   g_csr  [N_EDGES];
__device__ __align__(16) int   g_cnt  [N_NODES];
__device__ __align__(16) int   g_start[N_NODES];
__device__ __align__(16) int   g_cur  [N_NODES];
__device__ int g_total;

__device__ __forceinline__ uint32_t smem_u32(const void* p) {
    uint32_t a;
    asm("{ .reg .u64 t; cvta.to.shared.u64 t, %1; cvt.u32.u64 %0, t; }" : "=r"(a) : "l"(p));
    return a;
}

#define LDMX4(r0, r1, r2, r3, addr) \
    asm volatile("ldmatrix.sync.aligned.m8n8.x4.shared.b16 {%0,%1,%2,%3}, [%4];" \
                 : "=r"(r0), "=r"(r1), "=r"(r2), "=r"(r3) : "r"(addr))

#define MMA16816(d, a, b0, b1) \
    asm volatile("mma.sync.aligned.m16n8k16.row.col.f32.bf16.bf16.f32 " \
                 "{%0,%1,%2,%3}, {%4,%5,%6,%7}, {%8,%9}, {%0,%1,%2,%3};" \
                 : "+f"((d)[0]), "+f"((d)[1]), "+f"((d)[2]), "+f"((d)[3]) \
                 : "r"((a)[0]), "r"((a)[1]), "r"((a)[2]), "r"((a)[3]), \
                   "r"(b0), "r"(b1))

__device__ __forceinline__ void split_bf16(float v, unsigned short& hi, unsigned short& lo) {
    __nv_bfloat16 h = __float2bfloat16_rn(v);
    hi = __bfloat16_as_ushort(h);
    lo = __bfloat16_as_ushort(__float2bfloat16_rn(v - __bfloat162float(h)));
}

// ================= preprocessing =================
__global__ void zero_kernel(int* __restrict__ cnt, int* __restrict__ total) {
    int i = blockIdx.x * blockDim.x + threadIdx.x;
    if (i < N_NODES) cnt[i] = 0;
    if (i == 0) *total = 0;
}

__global__ void convert_hist_kernel(const int* __restrict__ ei32,
                                    int* __restrict__ src, int* __restrict__ dst,
                                    int* __restrict__ cnt) {
    int lane = threadIdx.x & 31;
    int hi = ei32[2 * lane + 1] | ei32[2 * (lane + 32) + 1];
    bool is64 = !__any_sync(0xffffffffu, hi != 0);

    int e = blockIdx.x * blockDim.x + threadIdx.x;
    if (e >= N_EDGES) return;
    int s, d;
    if (is64) { s = ei32[2 * e]; d = ei32[2 * (N_EDGES + e)]; }
    else      { s = ei32[e];     d = ei32[N_EDGES + e]; }
    src[e] = s;
    dst[e] = d;
    atomicAdd(&cnt[d], 1);
}

__global__ void dinv_seg_kernel(const int* __restrict__ cnt, float* __restrict__ dinv,
                                int* __restrict__ start, int* __restrict__ cur,
                                int* __restrict__ total) {
    int i = blockIdx.x * blockDim.x + threadIdx.x;
    if (i < N_NODES) {
        int c = cnt[i];
        dinv[i] = rsqrtf((float)c + 1.0f);
        int s = atomicAdd(total, c);
        start[i] = s;
        cur[i]   = s;
    }
}

__global__ void scatter_kernel(const int* __restrict__ src, const int* __restrict__ dst,
                               int* __restrict__ cur, int* __restrict__ csr) {
    int e = blockIdx.x * blockDim.x + threadIdx.x;
    if (e < N_EDGES) {
        int pos = atomicAdd(&cur[dst[e]], 1);
        csr[pos] = src[e];
    }
}

// ---- W pre-split: W[128,BN] fp32 -> whi/wlo [n][LDA] bf16, pad zeroed ----
__global__ void prep_w_kernel(const float* __restrict__ W, int BN,
                              __nv_bfloat16* __restrict__ whi,
                              __nv_bfloat16* __restrict__ wlo) {
    int idx = blockIdx.x * blockDim.x + threadIdx.x;  // over BN*LDA
    if (idx >= BN * LDA) return;
    int n = idx / LDA;
    int k = idx % LDA;
    unsigned short h = 0, l = 0;
    if (k < 128) split_bf16(W[(size_t)k * BN + n], h, l);
    whi[idx] = __ushort_as_bfloat16(h);
    wlo[idx] = __ushort_as_bfloat16(l);
}

// ================= GEMM: T' = (A @ W) * dinv[row] =================
// PACKED=0: A fp32 [M,128] (layer 1, split in kernel, no relu).
// PACKED=1: A given as hi/lo bf16 planes (layers 2,3; relu already applied).
template <int BN, bool PACKED>
__global__ __launch_bounds__(256)
void gemm_mma_kernel(const float* __restrict__ Afp,
                     const __nv_bfloat16* __restrict__ Ahi_g,
                     const __nv_bfloat16* __restrict__ Alo_g,
                     const __nv_bfloat16* __restrict__ Whi_g,
                     const __nv_bfloat16* __restrict__ Wlo_g,
                     const float* __restrict__ dinv,
                     float* __restrict__ T)
{
    constexpr int A_BYTES = 128 * LDA * 2;
    constexpr int B_BYTES = BN  * LDA * 2;
    constexpr int NCH     = BN / 8;

    extern __shared__ __align__(16) char smem[];
    __nv_bfloat16* Ahi = reinterpret_cast<__nv_bfloat16*>(smem);
    __nv_bfloat16* Alo = reinterpret_cast<__nv_bfloat16*>(smem + A_BYTES);
    __nv_bfloat16* Bhi = reinterpret_cast<__nv_bfloat16*>(smem + 2 * A_BYTES);
    __nv_bfloat16* Blo = reinterpret_cast<__nv_bfloat16*>(smem + 2 * A_BYTES + B_BYTES);

    const int tid   = threadIdx.x;
    const int wid   = tid >> 5;
    const int lane  = tid & 31;
    const int tile0 = blockIdx.x * 128;

    if (PACKED) {
        // pure copy: 128 rows x 256B per plane = 2048 u4 chunks per plane
        #pragma unroll
        for (int it = 0; it < 8; it++) {
            int f = it * 256 + tid;
            int r = f >> 4;
            int c = (f & 15) * 8;
            int gr = tile0 + r;
            if (gr >= N_NODES) gr = N_NODES - 1;
            *reinterpret_cast<uint4*>(&Ahi[r * LDA + c]) =
                *reinterpret_cast<const uint4*>(&Ahi_g[(size_t)gr * 128 + c]);
            *reinterpret_cast<uint4*>(&Alo[r * LDA + c]) =
                *reinterpret_cast<const uint4*>(&Alo_g[(size_t)gr * 128 + c]);
        }
    } else {
        #pragma unroll
        for (int it = 0; it < 16; it++) {
            int f  = it * 256 + tid;
            int r  = f >> 5;
            int c  = (f & 31) * 4;
            int gr = tile0 + r;
            if (gr >= N_NODES) gr = N_NODES - 1;
            float4 v = *reinterpret_cast<const float4*>(Afp + (size_t)gr * K_DIM + c);
            unsigned short h0, h1, h2, h3, l0, l1, l2, l3;
            split_bf16(v.x, h0, l0); split_bf16(v.y, h1, l1);
            split_bf16(v.z, h2, l2); split_bf16(v.w, h3, l3);
            u64 hp = (u64)h0 | ((u64)h1 << 16) | ((u64)h2 << 32) | ((u64)h3 << 48);
            u64 lp = (u64)l0 | ((u64)l1 << 16) | ((u64)l2 << 32) | ((u64)l3 << 48);
            *reinterpret_cast<u64*>(&Ahi[r * LDA + c]) = hp;
            *reinterpret_cast<u64*>(&Alo[r * LDA + c]) = lp;
        }
    }

    // B tiles: straight copy of pre-split planes (BN*17 u4 chunks per plane)
    for (int f = tid; f < BN * 17; f += 256) {
        int r = f / 17;
        int c = (f % 17) * 8;
        *reinterpret_cast<uint4*>(&Bhi[r * LDA + c]) =
            *reinterpret_cast<const uint4*>(&Whi_g[(size_t)r * LDA + c]);
        *reinterpret_cast<uint4*>(&Blo[r * LDA + c]) =
            *reinterpret_cast<const uint4*>(&Wlo_g[(size_t)r * LDA + c]);
    }
    __syncthreads();

    const uint32_t a_off = (uint32_t)((wid * 16 + (lane & 15)) * LDA + (lane >> 4) * 8) * 2;
    const uint32_t ahi_base = smem_u32(Ahi) + a_off;
    const uint32_t alo_base = smem_u32(Alo) + a_off;
    const uint32_t b_off = (uint32_t)(((lane & 7) + (lane >> 4) * 8) * LDA + ((lane >> 3) & 1) * 8) * 2;
    const uint32_t bhi_base = smem_u32(Bhi) + b_off;
    const uint32_t blo_base = smem_u32(Blo) + b_off;

    float acc[NCH][4];
    #pragma unroll
    for (int i = 0; i < NCH; i++)
        #pragma unroll
        for (int j = 0; j < 4; j++) acc[i][j] = 0.f;

    #pragma unroll
    for (int ks = 0; ks < 8; ks++) {
        const uint32_t kb = ks * 32;
        uint32_t ah[4], al[4];
        LDMX4(ah[0], ah[1], ah[2], ah[3], ahi_base + kb);
        LDMX4(al[0], al[1], al[2], al[3], alo_base + kb);
        #pragma unroll
        for (int nb = 0; nb < BN / 16; nb++) {
            const uint32_t nbo = (uint32_t)(nb * 16 * LDA) * 2 + kb;
            uint32_t bh[4], bl[4];
            LDMX4(bh[0], bh[1], bh[2], bh[3], bhi_base + nbo);
            LDMX4(bl[0], bl[1], bl[2], bl[3], blo_base + nbo);
            MMA16816(acc[2 * nb],     ah, bh[0], bh[1]);
            MMA16816(acc[2 * nb + 1], ah, bh[2], bh[3]);
            MMA16816(acc[2 * nb],     ah, bl[0], bl[1]);
            MMA16816(acc[2 * nb + 1], ah, bl[2], bl[3]);
            MMA16816(acc[2 * nb],     al, bh[0], bh[1]);
            MMA16816(acc[2 * nb + 1], al, bh[2], bh[3]);
        }
    }

    const int g = lane >> 2, t = lane & 3;
    const int rowA = tile0 + wid * 16 + g;
    const int rowB = rowA + 8;
    const float dvA = dinv[rowA < N_NODES ? rowA : N_NODES - 1];
    const float dvB = dinv[rowB < N_NODES ? rowB : N_NODES - 1];
    #pragma unroll
    for (int nc = 0; nc < NCH; nc++) {
        int col = nc * 8 + 2 * t;
        if (rowA < N_NODES)
            *reinterpret_cast<float2*>(T + (size_t)rowA * BN + col) =
                make_float2(acc[nc][0] * dvA, acc[nc][1] * dvA);
        if (rowB < N_NODES)
            *reinterpret_cast<float2*>(T + (size_t)rowB * BN + col) =
                make_float2(acc[nc][2] * dvB, acc[nc][3] * dvB);
    }
}

// ================= gather aggregation =================
// T' rows already scaled by dinv[src]. OUT = dinv[n]*(sum T'[s] + T'[n]) + b.
// MODE 0: fp32 out. MODE 1: relu -> split bf16 hi/lo planes (next layer input).
template <int F, int MODE>
__global__ __launch_bounds__(256)
void agg_kernel(const int* __restrict__ start, const int* __restrict__ cnt,
                const int* __restrict__ csr, const float* __restrict__ dinv,
                const float* __restrict__ T, const float* __restrict__ bias,
                float* __restrict__ OUT,
                __nv_bfloat16* __restrict__ Hhi, __nv_bfloat16* __restrict__ Hlo)
{
    constexpr int LPN = F / 4;
    int gid  = blockIdx.x * blockDim.x + threadIdx.x;
    int node = gid / LPN;
    int lane = gid % LPN;
    if (node >= N_NODES) return;

    const int s = start[node];
    const int c = cnt[node];
    const int off = lane * 4;

    // self term first (T'[node])
    float4 acc = *reinterpret_cast<const float4*>(T + (size_t)node * F + off);

    int j = 0;
    for (; j + 8 <= c; j += 8) {
        int sid[8];
        #pragma unroll
        for (int u = 0; u < 8; u++) sid[u] = csr[s + j + u];
        float4 v[8];
        #pragma unroll
        for (int u = 0; u < 8; u++)
            v[u] = *reinterpret_cast<const float4*>(T + (size_t)sid[u] * F + off);
        #pragma unroll
        for (int u = 0; u < 8; u++) {
            acc.x += v[u].x; acc.y += v[u].y; acc.z += v[u].z; acc.w += v[u].w;
        }
    }
    for (; j + 2 <= c; j += 2) {
        int s0 = csr[s + j], s1 = csr[s + j + 1];
        float4 v0 = *reinterpret_cast<const float4*>(T + (size_t)s0 * F + off);
        float4 v1 = *reinterpret_cast<const float4*>(T + (size_t)s1 * F + off);
        acc.x += v0.x + v1.x; acc.y += v0.y + v1.y;
        acc.z += v0.z + v1.z; acc.w += v0.w + v1.w;
    }
    if (j < c) {
        int s0 = csr[s + j];
        float4 v0 = *reinterpret_cast<const float4*>(T + (size_t)s0 * F + off);
        acc.x += v0.x; acc.y += v0.y; acc.z += v0.z; acc.w += v0.w;
    }

    float dv = dinv[node];
    float4 bv = *reinterpret_cast<const float4*>(bias + off);
    float4 o;
    o.x = fmaf(acc.x, dv, bv.x);
    o.y = fmaf(acc.y, dv, bv.y);
    o.z = fmaf(acc.z, dv, bv.z);
    o.w = fmaf(acc.w, dv, bv.w);

    if (MODE == 0) {
        *reinterpret_cast<float4*>(OUT + (size_t)node * F + off) = o;
    } else {
        o.x = fmaxf(o.x, 0.f); o.y = fmaxf(o.y, 0.f);
        o.z = fmaxf(o.z, 0.f); o.w = fmaxf(o.w, 0.f);
        unsigned short h0, h1, h2, h3, l0, l1, l2, l3;
        split_bf16(o.x, h0, l0); split_bf16(o.y, h1, l1);
        split_bf16(o.z, h2, l2); split_bf16(o.w, h3, l3);
        u64 hp = (u64)h0 | ((u64)h1 << 16) | ((u64)h2 << 32) | ((u64)h3 << 48);
        u64 lp = (u64)l0 | ((u64)l1 << 16) | ((u64)l2 << 32) | ((u64)l3 << 48);
        *reinterpret_cast<u64*>(&Hhi[(size_t)node * F + off]) = hp;
        *reinterpret_cast<u64*>(&Hlo[(size_t)node * F + off]) = lp;
    }
}

// ================= launch =================
extern "C" void kernel_launch(void* const* d_in, const int* in_sizes, int n_in,
                              void* d_out, int out_size)
{
    const float* x    = (const float*)d_in[0];
    const int*   ei32 = (const int*)d_in[1];
    const float* W1 = (const float*)d_in[2];
    const float* b1 = (const float*)d_in[3];
    const float* W2 = (const float*)d_in[4];
    const float* b2 = (const float*)d_in[5];
    const float* W3 = (const float*)d_in[6];
    const float* b3 = (const float*)d_in[7];
    float* out = (float*)d_out;

    float *dinv, *t;
    __nv_bfloat16 *hhi, *hlo, *h2hi, *h2lo, *whi, *wlo;
    int *src, *dst, *csr, *cnt, *start, *cur, *total;
    cudaGetSymbolAddress((void**)&dinv,  g_dinv);
    cudaGetSymbolAddress((void**)&t,     g_t);
    cudaGetSymbolAddress((void**)&hhi,   g_hhi);
    cudaGetSymbolAddress((void**)&hlo,   g_hlo);
    cudaGetSymbolAddress((void**)&h2hi,  g_h2hi);
    cudaGetSymbolAddress((void**)&h2lo,  g_h2lo);
    cudaGetSymbolAddress((void**)&whi,   g_whi);
    cudaGetSymbolAddress((void**)&wlo,   g_wlo);
    cudaGetSymbolAddress((void**)&src,   g_src);
    cudaGetSymbolAddress((void**)&dst,   g_dst);
    cudaGetSymbolAddress((void**)&csr,   g_csr);
    cudaGetSymbolAddress((void**)&cnt,   g_cnt);
    cudaGetSymbolAddress((void**)&start, g_start);
    cudaGetSymbolAddress((void**)&cur,   g_cur);
    cudaGetSymbolAddress((void**)&total, g_total);

    const int TB = 256;
    const int NGRID = (N_NODES + TB - 1) / TB;
    const int EGRID = (N_EDGES + TB - 1) / TB;
    const int WGRID = (128 * LDA + TB - 1) / TB;

    zero_kernel        <<<NGRID, TB>>>(cnt, total);
    convert_hist_kernel<<<EGRID, TB>>>(ei32, src, dst, cnt);
    dinv_seg_kernel    <<<NGRID, TB>>>(cnt, dinv, start, cur, total);
    scatter_kernel     <<<EGRID, TB>>>(src, dst, cur, csr);

    prep_w_kernel<<<WGRID, TB>>>(W1, 128, whi,                 wlo);
    prep_w_kernel<<<WGRID, TB>>>(W2, 128, whi + 128 * LDA,     wlo + 128 * LDA);
    prep_w_kernel<<<WGRID, TB>>>(W3, 64,  whi + 2 * 128 * LDA, wlo + 2 * 128 * LDA);

    const int GTILES = (N_NODES + 127) / 128;
    const int SMEM128 = 4 * (128 * LDA * 2);
    const int SMEM64  = 2 * (128 * LDA * 2) + 2 * (64 * LDA * 2);
    static bool attr_done = false;
    if (!attr_done) {
        cudaFuncSetAttribute(gemm_mma_kernel<128, false>,
                             cudaFuncAttributeMaxDynamicSharedMemorySize, SMEM128);
        cudaFuncSetAttribute(gemm_mma_kernel<128, true>,
                             cudaFuncAttributeMaxDynamicSharedMemorySize, SMEM128);
        cudaFuncSetAttribute(gemm_mma_kernel<64, true>,
                             cudaFuncAttributeMaxDynamicSharedMemorySize, SMEM64);
        attr_done = true;
    }

    const int agrid128 = (N_NODES * 32 + TB - 1) / TB;
    const int agrid64  = (N_NODES * 16 + TB - 1) / TB;

    // Layer 1 (A fp32)
    gemm_mma_kernel<128, false><<<GTILES, 256, SMEM128>>>(
        x, nullptr, nullptr, whi, wlo, dinv, t);
    agg_kernel<128, 1><<<agrid128, TB>>>(start, cnt, csr, dinv, t, b1,
                                         nullptr, hhi, hlo);
    // Layer 2 (A packed planes)
    gemm_mma_kernel<128, true><<<GTILES, 256, SMEM128>>>(
        nullptr, hhi, hlo, whi + 128 * LDA, wlo + 128 * LDA, dinv, t);
    agg_kernel<128, 1><<<agrid128, TB>>>(start, cnt, csr, dinv, t, b2,
                                         nullptr, h2hi, h2lo);
    // Layer 3 (A packed planes, 64-ch out, fp32)
    gemm_mma_kernel<64, true><<<GTILES, 256, SMEM64>>>(
        nullptr, h2hi, h2lo, whi + 2 * 128 * LDA, wlo + 2 * 128 * LDA, dinv, t);
    agg_kernel<64, 0><<<agrid64, TB>>>(start, cnt, csr, dinv, t, b3,
                                       out, nullptr, nullptr);
}

// round 14
// speedup vs baseline: 1.3226x; 1.0019x over previous
#include <cuda_runtime.h>
#include <cuda_bf16.h>
#include <cstdint>

#define N_NODES 100000
#define N_EDGES 800000
#define K_DIM   128
#define LDA     136

typedef unsigned long long u64;

// -------- scratch (device globals; no allocation allowed) --------
__device__ __align__(16) float g_dinv [N_NODES];
__device__ __align__(16) float g_t    [N_NODES * 128];   // T' = (A@W)*dinv[row]
__device__ __align__(16) __nv_bfloat16 g_hhi[N_NODES * 128];
__device__ __align__(16) __nv_bfloat16 g_hlo[N_NODES * 128];
__device__ __align__(16) __nv_bfloat16 g_h2hi[N_NODES * 128];
__device__ __align__(16) __nv_bfloat16 g_h2lo[N_NODES * 128];
__device__ __align__(16) __nv_bfloat16 g_whi[3 * 128 * LDA];
__device__ __align__(16) __nv_bfloat16 g_wlo[3 * 128 * LDA];
__device__ __align__(16) int   g_src  [N_EDGES];
__device__ __align__(16) int   g_dst  [N_EDGES];
__device__ __align__(16) int   g_csr  [N_EDGES];
__device__ __align__(16) int   g_cnt  [N_NODES];
__device__ __align__(16) int   g_start[N_NODES];
__device__ __align__(16) int   g_cur  [N_NODES];
__device__ int g_total;

__device__ __forceinline__ uint32_t smem_u32(const void* p) {
    uint32_t a;
    asm("{ .reg .u64 t; cvta.to.shared.u64 t, %1; cvt.u32.u64 %0, t; }" : "=r"(a) : "l"(p));
    return a;
}

#define LDMX4(r0, r1, r2, r3, addr) \
    asm volatile("ldmatrix.sync.aligned.m8n8.x4.shared.b16 {%0,%1,%2,%3}, [%4];" \
                 : "=r"(r0), "=r"(r1), "=r"(r2), "=r"(r3) : "r"(addr))

#define MMA16816(d, a, b0, b1) \
    asm volatile("mma.sync.aligned.m16n8k16.row.col.f32.bf16.bf16.f32 " \
                 "{%0,%1,%2,%3}, {%4,%5,%6,%7}, {%8,%9}, {%0,%1,%2,%3};" \
                 : "+f"((d)[0]), "+f"((d)[1]), "+f"((d)[2]), "+f"((d)[3]) \
                 : "r"((a)[0]), "r"((a)[1]), "r"((a)[2]), "r"((a)[3]), \
                   "r"(b0), "r"(b1))

__device__ __forceinline__ void split_bf16(float v, unsigned short& hi, unsigned short& lo) {
    __nv_bfloat16 h = __float2bfloat16_rn(v);
    hi = __bfloat16_as_ushort(h);
    lo = __bfloat16_as_ushort(__float2bfloat16_rn(v - __bfloat162float(h)));
}

// ================= preprocessing =================
__global__ void zero_kernel(int* __restrict__ cnt, int* __restrict__ total) {
    int i = blockIdx.x * blockDim.x + threadIdx.x;
    if (i < N_NODES) cnt[i] = 0;
    if (i == 0) *total = 0;
}

__global__ void convert_hist_kernel(const int* __restrict__ ei32,
                                    int* __restrict__ src, int* __restrict__ dst,
                                    int* __restrict__ cnt) {
    int lane = threadIdx.x & 31;
    int hi = ei32[2 * lane + 1] | ei32[2 * (lane + 32) + 1];
    bool is64 = !__any_sync(0xffffffffu, hi != 0);

    int e = blockIdx.x * blockDim.x + threadIdx.x;
    if (e >= N_EDGES) return;
    int s, d;
    if (is64) { s = ei32[2 * e]; d = ei32[2 * (N_EDGES + e)]; }
    else      { s = ei32[e];     d = ei32[N_EDGES + e]; }
    src[e] = s;
    dst[e] = d;
    atomicAdd(&cnt[d], 1);
}

__global__ void dinv_seg_kernel(const int* __restrict__ cnt, float* __restrict__ dinv,
                                int* __restrict__ start, int* __restrict__ cur,
                                int* __restrict__ total) {
    int i = blockIdx.x * blockDim.x + threadIdx.x;
    if (i < N_NODES) {
        int c = cnt[i];
        dinv[i] = rsqrtf((float)c + 1.0f);
        int s = atomicAdd(total, c);
        start[i] = s;
        cur[i]   = s;
    }
}

__global__ void scatter_kernel(const int* __restrict__ src, const int* __restrict__ dst,
                               int* __restrict__ cur, int* __restrict__ csr) {
    int e = blockIdx.x * blockDim.x + threadIdx.x;
    if (e < N_EDGES) {
        int pos = atomicAdd(&cur[dst[e]], 1);
        csr[pos] = src[e];
    }
}

// ---- W pre-split: W[128,BN] fp32 -> whi/wlo [n][LDA] bf16, pad zeroed ----
__global__ void prep_w_kernel(const float* __restrict__ W, int BN,
                              __nv_bfloat16* __restrict__ whi,
                              __nv_bfloat16* __restrict__ wlo) {
    int idx = blockIdx.x * blockDim.x + threadIdx.x;  // over BN*LDA
    if (idx >= BN * LDA) return;
    int n = idx / LDA;
    int k = idx % LDA;
    unsigned short h = 0, l = 0;
    if (k < 128) split_bf16(W[(size_t)k * BN + n], h, l);
    whi[idx] = __ushort_as_bfloat16(h);
    wlo[idx] = __ushort_as_bfloat16(l);
}

// ================= GEMM: T' = (A @ W) * dinv[row] =================
// PACKED=0: A fp32 [M,128] (layer 1, split in kernel, no relu).
// PACKED=1: A given as hi/lo bf16 planes (layers 2,3; relu already applied).
template <int BN, bool PACKED>
__global__ __launch_bounds__(256)
void gemm_mma_kernel(const float* __restrict__ Afp,
                     const __nv_bfloat16* __restrict__ Ahi_g,
                     const __nv_bfloat16* __restrict__ Alo_g,
                     const __nv_bfloat16* __restrict__ Whi_g,
                     const __nv_bfloat16* __restrict__ Wlo_g,
                     const float* __restrict__ dinv,
                     float* __restrict__ T)
{
    constexpr int A_BYTES = 128 * LDA * 2;
    constexpr int B_BYTES = BN  * LDA * 2;
    constexpr int NCH     = BN / 8;

    extern __shared__ __align__(16) char smem[];
    __nv_bfloat16* Ahi = reinterpret_cast<__nv_bfloat16*>(smem);
    __nv_bfloat16* Alo = reinterpret_cast<__nv_bfloat16*>(smem + A_BYTES);
    __nv_bfloat16* Bhi = reinterpret_cast<__nv_bfloat16*>(smem + 2 * A_BYTES);
    __nv_bfloat16* Blo = reinterpret_cast<__nv_bfloat16*>(smem + 2 * A_BYTES + B_BYTES);

    const int tid   = threadIdx.x;
    const int wid   = tid >> 5;
    const int lane  = tid & 31;
    const int tile0 = blockIdx.x * 128;

    if (PACKED) {
        // pure copy: 128 rows x 256B per plane = 2048 u4 chunks per plane
        #pragma unroll
        for (int it = 0; it < 8; it++) {
            int f = it * 256 + tid;
            int r = f >> 4;
            int c = (f & 15) * 8;
            int gr = tile0 + r;
            if (gr >= N_NODES) gr = N_NODES - 1;
            *reinterpret_cast<uint4*>(&Ahi[r * LDA + c]) =
                *reinterpret_cast<const uint4*>(&Ahi_g[(size_t)gr * 128 + c]);
            *reinterpret_cast<uint4*>(&Alo[r * LDA + c]) =
                *reinterpret_cast<const uint4*>(&Alo_g[(size_t)gr * 128 + c]);
        }
    } else {
        #pragma unroll
        for (int it = 0; it < 16; it++) {
            int f  = it * 256 + tid;
            int r  = f >> 5;
            int c  = (f & 31) * 4;
            int gr = tile0 + r;
            if (gr >= N_NODES) gr = N_NODES - 1;
            float4 v = *reinterpret_cast<const float4*>(Afp + (size_t)gr * K_DIM + c);
            unsigned short h0, h1, h2, h3, l0, l1, l2, l3;
            split_bf16(v.x, h0, l0); split_bf16(v.y, h1, l1);
            split_bf16(v.z, h2, l2); split_bf16(v.w, h3, l3);
            u64 hp = (u64)h0 | ((u64)h1 << 16) | ((u64)h2 << 32) | ((u64)h3 << 48);
            u64 lp = (u64)l0 | ((u64)l1 << 16) | ((u64)l2 << 32) | ((u64)l3 << 48);
            *reinterpret_cast<u64*>(&Ahi[r * LDA + c]) = hp;
            *reinterpret_cast<u64*>(&Alo[r * LDA + c]) = lp;
        }
    }

    // B tiles: straight copy of pre-split planes (BN*17 u4 chunks per plane)
    for (int f = tid; f < BN * 17; f += 256) {
        int r = f / 17;
        int c = (f % 17) * 8;
        *reinterpret_cast<uint4*>(&Bhi[r * LDA + c]) =
            *reinterpret_cast<const uint4*>(&Whi_g[(size_t)r * LDA + c]);
        *reinterpret_cast<uint4*>(&Blo[r * LDA + c]) =
            *reinterpret_cast<const uint4*>(&Wlo_g[(size_t)r * LDA + c]);
    }
    __syncthreads();

    const uint32_t a_off = (uint32_t)((wid * 16 + (lane & 15)) * LDA + (lane >> 4) * 8) * 2;
    const uint32_t ahi_base = smem_u32(Ahi) + a_off;
    const uint32_t alo_base = smem_u32(Alo) + a_off;
    const uint32_t b_off = (uint32_t)(((lane & 7) + (lane >> 4) * 8) * LDA + ((lane >> 3) & 1) * 8) * 2;
    const uint32_t bhi_base = smem_u32(Bhi) + b_off;
    const uint32_t blo_base = smem_u32(Blo) + b_off;

    float acc[NCH][4];
    #pragma unroll
    for (int i = 0; i < NCH; i++)
        #pragma unroll
        for (int j = 0; j < 4; j++) acc[i][j] = 0.f;

    #pragma unroll
    for (int ks = 0; ks < 8; ks++) {
        const uint32_t kb = ks * 32;
        uint32_t ah[4], al[4];
        LDMX4(ah[0], ah[1], ah[2], ah[3], ahi_base + kb);
        LDMX4(al[0], al[1], al[2], al[3], alo_base + kb);
        #pragma unroll
        for (int nb = 0; nb < BN / 16; nb++) {
            const uint32_t nbo = (uint32_t)(nb * 16 * LDA) * 2 + kb;
            uint32_t bh[4], bl[4];
            LDMX4(bh[0], bh[1], bh[2], bh[3], bhi_base + nbo);
            LDMX4(bl[0], bl[1], bl[2], bl[3], blo_base + nbo);
            MMA16816(acc[2 * nb],     ah, bh[0], bh[1]);
            MMA16816(acc[2 * nb + 1], ah, bh[2], bh[3]);
            MMA16816(acc[2 * nb],     ah, bl[0], bl[1]);
            MMA16816(acc[2 * nb + 1], ah, bl[2], bl[3]);
            MMA16816(acc[2 * nb],     al, bh[0], bh[1]);
            MMA16816(acc[2 * nb + 1], al, bh[2], bh[3]);
        }
    }

    const int g = lane >> 2, t = lane & 3;
    const int rowA = tile0 + wid * 16 + g;
    const int rowB = rowA + 8;
    const float dvA = dinv[rowA < N_NODES ? rowA : N_NODES - 1];
    const float dvB = dinv[rowB < N_NODES ? rowB : N_NODES - 1];
    #pragma unroll
    for (int nc = 0; nc < NCH; nc++) {
        int col = nc * 8 + 2 * t;
        if (rowA < N_NODES)
            *reinterpret_cast<float2*>(T + (size_t)rowA * BN + col) =
                make_float2(acc[nc][0] * dvA, acc[nc][1] * dvA);
        if (rowB < N_NODES)
            *reinterpret_cast<float2*>(T + (size_t)rowB * BN + col) =
                make_float2(acc[nc][2] * dvB, acc[nc][3] * dvB);
    }
}

// ================= gather aggregation =================
// T' rows already scaled by dinv[src]. OUT = dinv[n]*(sum T'[s] + T'[n]) + b.
// MODE 0: fp32 out. MODE 1: relu -> split bf16 hi/lo planes (next layer input).
template <int F, int MODE>
__global__ __launch_bounds__(256)
void agg_kernel(const int* __restrict__ start, const int* __restrict__ cnt,
                const int* __restrict__ csr, const float* __restrict__ dinv,
                const float* __restrict__ T, const float* __restrict__ bias,
                float* __restrict__ OUT,
                __nv_bfloat16* __restrict__ Hhi, __nv_bfloat16* __restrict__ Hlo)
{
    constexpr int LPN = F / 4;
    int gid  = blockIdx.x * blockDim.x + threadIdx.x;
    int node = gid / LPN;
    int lane = gid % LPN;
    if (node >= N_NODES) return;

    const int s = start[node];
    const int c = cnt[node];
    const int off = lane * 4;

    // self term first (T'[node])
    float4 acc = *reinterpret_cast<const float4*>(T + (size_t)node * F + off);

    int j = 0;
    for (; j + 8 <= c; j += 8) {
        int sid[8];
        #pragma unroll
        for (int u = 0; u < 8; u++) sid[u] = csr[s + j + u];
        float4 v[8];
        #pragma unroll
        for (int u = 0; u < 8; u++)
            v[u] = *reinterpret_cast<const float4*>(T + (size_t)sid[u] * F + off);
        #pragma unroll
        for (int u = 0; u < 8; u++) {
            acc.x += v[u].x; acc.y += v[u].y; acc.z += v[u].z; acc.w += v[u].w;
        }
    }
    for (; j + 2 <= c; j += 2) {
        int s0 = csr[s + j], s1 = csr[s + j + 1];
        float4 v0 = *reinterpret_cast<const float4*>(T + (size_t)s0 * F + off);
        float4 v1 = *reinterpret_cast<const float4*>(T + (size_t)s1 * F + off);
        acc.x += v0.x + v1.x; acc.y += v0.y + v1.y;
        acc.z += v0.z + v1.z; acc.w += v0.w + v1.w;
    }
    if (j < c) {
        int s0 = csr[s + j];
        float4 v0 = *reinterpret_cast<const float4*>(T + (size_t)s0 * F + off);
        acc.x += v0.x; acc.y += v0.y; acc.z += v0.z; acc.w += v0.w;
    }

    float dv = dinv[node];
    float4 bv = *reinterpret_cast<const float4*>(bias + off);
    float4 o;
    o.x = fmaf(acc.x, dv, bv.x);
    o.y = fmaf(acc.y, dv, bv.y);
    o.z = fmaf(acc.z, dv, bv.z);
    o.w = fmaf(acc.w, dv, bv.w);

    if (MODE == 0) {
        *reinterpret_cast<float4*>(OUT + (size_t)node * F + off) = o;
    } else {
        o.x = fmaxf(o.x, 0.f); o.y = fmaxf(o.y, 0.f);
        o.z = fmaxf(o.z, 0.f); o.w = fmaxf(o.w, 0.f);
        unsigned short h0, h1, h2, h3, l0, l1, l2, l3;
        split_bf16(o.x, h0, l0); split_bf16(o.y, h1, l1);
        split_bf16(o.z, h2, l2); split_bf16(o.w, h3, l3);
        u64 hp = (u64)h0 | ((u64)h1 << 16) | ((u64)h2 << 32) | ((u64)h3 << 48);
        u64 lp = (u64)l0 | ((u64)l1 << 16) | ((u64)l2 << 32) | ((u64)l3 << 48);
        *reinterpret_cast<u64*>(&Hhi[(size_t)node * F + off]) = hp;
        *reinterpret_cast<u64*>(&Hlo[(size_t)node * F + off]) = lp;
    }
}

// ================= launch =================
extern "C" void kernel_launch(void* const* d_in, const int* in_sizes, int n_in,
                              void* d_out, int out_size)
{
    const float* x    = (const float*)d_in[0];
    const int*   ei32 = (const int*)d_in[1];
    const float* W1 = (const float*)d_in[2];
    const float* b1 = (const float*)d_in[3];
    const float* W2 = (const float*)d_in[4];
    const float* b2 = (const float*)d_in[5];
    const float* W3 = (const float*)d_in[6];
    const float* b3 = (const float*)d_in[7];
    float* out = (float*)d_out;

    float *dinv, *t;
    __nv_bfloat16 *hhi, *hlo, *h2hi, *h2lo, *whi, *wlo;
    int *src, *dst, *csr, *cnt, *start, *cur, *total;
    cudaGetSymbolAddress((void**)&dinv,  g_dinv);
    cudaGetSymbolAddress((void**)&t,     g_t);
    cudaGetSymbolAddress((void**)&hhi,   g_hhi);
    cudaGetSymbolAddress((void**)&hlo,   g_hlo);
    cudaGetSymbolAddress((void**)&h2hi,  g_h2hi);
    cudaGetSymbolAddress((void**)&h2lo,  g_h2lo);
    cudaGetSymbolAddress((void**)&whi,   g_whi);
    cudaGetSymbolAddress((void**)&wlo,   g_wlo);
    cudaGetSymbolAddress((void**)&src,   g_src);
    cudaGetSymbolAddress((void**)&dst,   g_dst);
    cudaGetSymbolAddress((void**)&csr,   g_csr);
    cudaGetSymbolAddress((void**)&cnt,   g_cnt);
    cudaGetSymbolAddress((void**)&start, g_start);
    cudaGetSymbolAddress((void**)&cur,   g_cur);
    cudaGetSymbolAddress((void**)&total, g_total);

    const int TB = 256;
    const int NGRID = (N_NODES + TB - 1) / TB;
    const int EGRID = (N_EDGES + TB - 1) / TB;
    const int WGRID = (128 * LDA + TB - 1) / TB;

    zero_kernel        <<<NGRID, TB>>>(cnt, total);
    convert_hist_kernel<<<EGRID, TB>>>(ei32, src, dst, cnt);
    dinv_seg_kernel    <<<NGRID, TB>>>(cnt, dinv, start, cur, total);
    scatter_kernel     <<<EGRID, TB>>>(src, dst, cur, csr);

    prep_w_kernel<<<WGRID, TB>>>(W1, 128, whi,                 wlo);
    prep_w_kernel<<<WGRID, TB>>>(W2, 128, whi + 128 * LDA,     wlo + 128 * LDA);
    prep_w_kernel<<<WGRID, TB>>>(W3, 64,  whi + 2 * 128 * LDA, wlo + 2 * 128 * LDA);

    const int GTILES = (N_NODES + 127) / 128;
    const int SMEM128 = 4 * (128 * LDA * 2);
    const int SMEM64  = 2 * (128 * LDA * 2) + 2 * (64 * LDA * 2);
    static bool attr_done = false;
    if (!attr_done) {
        cudaFuncSetAttribute(gemm_mma_kernel<128, false>,
                             cudaFuncAttributeMaxDynamicSharedMemorySize, SMEM128);
        cudaFuncSetAttribute(gemm_mma_kernel<128, true>,
                             cudaFuncAttributeMaxDynamicSharedMemorySize, SMEM128);
        cudaFuncSetAttribute(gemm_mma_kernel<64, true>,
                             cudaFuncAttributeMaxDynamicSharedMemorySize, SMEM64);
        attr_done = true;
    }

    const int agrid128 = (N_NODES * 32 + TB - 1) / TB;
    const int agrid64  = (N_NODES * 16 + TB - 1) / TB;

    // Layer 1 (A fp32)
    gemm_mma_kernel<128, false><<<GTILES, 256, SMEM128>>>(
        x, nullptr, nullptr, whi, wlo, dinv, t);
    agg_kernel<128, 1><<<agrid128, TB>>>(start, cnt, csr, dinv, t, b1,
                                         nullptr, hhi, hlo);
    // Layer 2 (A packed planes)
    gemm_mma_kernel<128, true><<<GTILES, 256, SMEM128>>>(
        nullptr, hhi, hlo, whi + 128 * LDA, wlo + 128 * LDA, dinv, t);
    agg_kernel<128, 1><<<agrid128, TB>>>(start, cnt, csr, dinv, t, b2,
                                         nullptr, h2hi, h2lo);
    // Layer 3 (A packed planes, 64-ch out, fp32)
    gemm_mma_kernel<64, true><<<GTILES, 256, SMEM64>>>(
        nullptr, h2hi, h2lo, whi + 2 * 128 * LDA, wlo + 2 * 128 * LDA, dinv, t);
    agg_kernel<64, 0><<<agrid64, TB>>>(start, cnt, csr, dinv, t, b3,
                                       out, nullptr, nullptr);
}